// round 5
// baseline (speedup 1.0000x reference)
#include <cuda_runtime.h>

// Problem constants: B=4, N=128, M=128, D=256, BD=1024
#define Bsz 4
#define Nn  128
#define Mm  128
#define Dd  256
#define BD  1024

// Scratch: allocation-free per harness rules -> __device__ global.
__device__ float g_Aw[Dd * Dd];          // 256 KB: Aw[d,e] = sum_k A[d,e,k]*W[k]

// ---------------------------------------------------------------------------
// Kernel 1 (the 268 MB pass): Aw[de] = dot(A[de, 0:1024], W[0:1024])
// EXACT R2 configuration (measured 42.4us @ 81.1% DRAM): one warp per (d,e)
// row, 8 float4 loads per lane, 8 warps/block, 8192 blocks, __ldcs streaming.
// ---------------------------------------------------------------------------
__global__ void __launch_bounds__(256) k_reduce_A(const float* __restrict__ A,
                                                  const float* __restrict__ W) {
    __shared__ float4 ws[BD / 4];  // 4 KB staged W
    int tid = threadIdx.x;
    ws[tid] = ((const float4*)W)[tid];
    __syncthreads();

    int warp = tid >> 5;
    int lane = tid & 31;
    long de = (long)blockIdx.x * 8 + warp;          // 8 warps/block, 8192 blocks
    const float4* a = (const float4*)(A + de * (long)BD);

    float sum = 0.0f;
#pragma unroll
    for (int i = 0; i < 8; i++) {
        float4 av = __ldcs(&a[lane + 32 * i]);      // non-temporal stream
        float4 wv = ws[lane + 32 * i];
        sum += av.x * wv.x + av.y * wv.y + av.z * wv.z + av.w * wv.w;
    }
#pragma unroll
    for (int o = 16; o; o >>= 1)
        sum += __shfl_xor_sync(0xFFFFFFFFu, sum, o);
    if (lane == 0) g_Aw[de] = sum;
}

// ---------------------------------------------------------------------------
// Kernel 2 (fused epilogue): per block (bat, 4 output rows n0..n0+3):
//   T[i][e] = sum_d X[bat,n0+i,d] * Aw[d][e]        (T strip kept in smem)
//   S[i][m] = sum_e T[i][e] * Y[bat,m,e] + bias
// Grid = 128 blocks (4 bat x 32 n-tiles), 256 threads.
// Aw rows are read coalesced from L2 (hot after kernel 1's stores).
// ---------------------------------------------------------------------------
__global__ void __launch_bounds__(256) k_fused_TS(const float* __restrict__ X,
                                                   const float* __restrict__ Y,
                                                   const float* __restrict__ bias,
                                                   float* __restrict__ out) {
    __shared__ float xs[4][Dd];          // 4 KB: X strip
    __shared__ float ts[4][Dd + 2];      // ~4 KB: T strip
    __shared__ float ys[32][Dd + 1];     // ~33 KB: Y tile (padded: conflict-free col reads)
    __shared__ float sp[4][36];          // partial sums (half-split reduce)

    int tid = threadIdx.x;
    int bat = blockIdx.y;
    int n0 = blockIdx.x * 4;

    // ---- Stage X strip: 4 rows x 64 float4 = 256 float4 -> 1 per thread
    {
        int r = tid >> 6, c4 = tid & 63;
        float4 v = ((const float4*)(X + ((long)bat * Nn + n0 + r) * Dd))[c4];
        xs[r][c4 * 4 + 0] = v.x; xs[r][c4 * 4 + 1] = v.y;
        xs[r][c4 * 4 + 2] = v.z; xs[r][c4 * 4 + 3] = v.w;
    }
    __syncthreads();

    // ---- T phase: thread e = tid computes T[0..3][e]. Aw rows coalesced.
    {
        float a0 = 0.f, a1 = 0.f, a2 = 0.f, a3 = 0.f;
        const float* awp = g_Aw + tid;
#pragma unroll 4
        for (int d = 0; d < Dd; d++) {
            float aw = awp[d * Dd];              // L2-hot, coalesced across threads
            a0 += xs[0][d] * aw;                 // xs[.][d]: smem broadcast
            a1 += xs[1][d] * aw;
            a2 += xs[2][d] * aw;
            a3 += xs[3][d] * aw;
        }
        ts[0][tid] = a0; ts[1][tid] = a1; ts[2][tid] = a2; ts[3][tid] = a3;
    }
    float bv = bias[0];
    __syncthreads();

    // ---- S phase: 4 m-tiles of 32. Thread = (half, i, m); each half sums 128 e.
    int half = tid >> 7;          // 0/1
    int i    = (tid >> 5) & 3;    // output row within strip
    int m    = tid & 31;          // m within tile
    int e0   = half * 128;

    const float* Yb = Y + (long)bat * Mm * Dd;
    float* ob = out + (long)bat * Nn * Mm + (long)(n0 + i) * Mm;

    for (int mt = 0; mt < 4; mt++) {
        // Stage Y tile: 32 rows x 64 float4 = 2048 float4 -> 8 per thread
        for (int idx = tid; idx < 32 * 64; idx += 256) {
            int r = idx >> 6, c4 = idx & 63;
            float4 v = ((const float4*)(Yb + (long)(mt * 32 + r) * Dd))[c4];
            ys[r][c4 * 4 + 0] = v.x; ys[r][c4 * 4 + 1] = v.y;
            ys[r][c4 * 4 + 2] = v.z; ys[r][c4 * 4 + 3] = v.w;
        }
        __syncthreads();

        float s = 0.f;
#pragma unroll 8
        for (int e = e0; e < e0 + 128; e++)
            s += ts[i][e] * ys[m][e];            // ts broadcast; ys stride-257: no conflicts

        if (half == 0) sp[i][m] = s;
        __syncthreads();
        if (half == 1)
            ob[mt * 32 + m] = sp[i][m] + s + bv;
        __syncthreads();                          // protect ys & sp before next tile
    }
}

// ---------------------------------------------------------------------------
// Launch. Input order (metadata): X, Y, A, W, b. Output fp32 [B,N,M].
// Graph-capturable: kernel launches only, no sync/alloc. No PDL (regressed R3).
// ---------------------------------------------------------------------------
extern "C" void kernel_launch(void* const* d_in, const int* in_sizes, int n_in,
                              void* d_out, int out_size) {
    const float* X = (const float*)d_in[0];
    const float* Y = (const float*)d_in[1];
    const float* A = (const float*)d_in[2];
    const float* W = (const float*)d_in[3];
    const float* b = (const float*)d_in[4];
    float* out = (float*)d_out;

    // 1) Aw = A contracted with W over k: 65536 (d,e) pairs, 8 warps/block
    k_reduce_A<<<(Dd * Dd) / 8, 256>>>(A, W);

    // 2) Fused (X@Aw)@Y^T + bias: 128 blocks (32 n-tiles x 4 batches)
    {
        dim3 grd(Nn / 4, Bsz);
        k_fused_TS<<<grd, 256>>>(X, Y, b, out);
    }
}